// round 11
// baseline (speedup 1.0000x reference)
#include <cuda_runtime.h>
#include <math.h>

// Problem constants: B=2, L=1024, H=8, E=64, n_top=35 (5*ceil(ln 1024))
#define B_  2
#define L_  1024
#define H_  8
#define E_  64
#define BH_ 16
#define NT_ 35      // top-k per half
#define NS_ 70      // total selected columns
#define SCALE_ 0.125f

// -------- static scratch (no allocations allowed) --------
// Invariant: g_amp2_t and g_usel are ZERO at kernel_launch entry (zero-init at
// module load; topk_kernel re-zeroes them every run after/before use).
__device__ float g_amp2_t[BH_ * L_];            // corr amplitudes^2 (atomic accum)
__device__ float g_amp2_tf[BH_ * L_];           // tf-query norms^2 (overwritten)
__device__ float g_scores[BH_ * NS_ * L_];      // overwritten each run
__device__ int   g_selidx[BH_ * NS_];           // [0..34]=idx_t, [35..69]=idx_tf
__device__ float g_usel[BH_ * 71 * E_];         // row 70 = bias row bv

__device__ __forceinline__ float2 cmulf(float2 a, float2 b) {
    return make_float2(a.x * b.x - a.y * b.y, a.x * b.y + a.y * b.x);
}

// Kernel 1: blocks [0,1024): FFT circular correlation per channel (b,h,e),
// atomic-accumulating ac^2 into g_amp2_t. blocks [1024,1040): tf-query row
// norms^2 per (b,h), direct store into g_amp2_tf (no zero needed).
__global__ void __launch_bounds__(256) corr_tf_kernel(const float* __restrict__ q,
                                                      const float* __restrict__ k,
                                                      const float* __restrict__ tfq) {
    __shared__ float2 bufA[L_];
    __shared__ float2 bufB[L_];
    int tid = threadIdx.x;

    if (blockIdx.x >= 1024) {
        // ---- tf-norm role ----
        int bh = blockIdx.x - 1024;
        int b = bh >> 3, h = bh & 7;
        #pragma unroll
        for (int jj = 0; jj < 4; jj++) {
            int l = tid + jj * 256;
            const float4* p = (const float4*)(tfq + (((size_t)(b * L_ + l) * H_ + h) * E_));
            float s = 0.f;
            #pragma unroll
            for (int j = 0; j < 16; j++) {
                float4 x = p[j];
                s += x.x * x.x + x.y * x.y + x.z * x.z + x.w * x.w;
            }
            g_amp2_tf[bh * L_ + l] = s;
        }
        return;
    }

    // ---- corr role ----
    int ch = blockIdx.x;            // b*512 + h*64 + e
    int e  = ch & 63;
    int bh = ch >> 6;
    int h  = bh & 7;
    int b  = bh >> 3;

    size_t base = (size_t)b * (L_ * H_ * E_) + (size_t)h * E_ + e;
    #pragma unroll
    for (int jj = 0; jj < 4; jj++) {
        int l = tid + jj * 256;
        bufA[l] = make_float2(q[base + (size_t)l * (H_ * E_)],
                              k[base + (size_t)l * (H_ * E_)]);
    }
    __syncthreads();

    float2* X = bufA;
    float2* Y = bufB;

    #pragma unroll
    for (int stage = 0; stage < 5; stage++) {
        int s2 = 2 * stage;
        int Ns = 1 << s2;
        int j = tid;
        float2 v0 = X[j];
        float2 v1 = X[j + 256];
        float2 v2 = X[j + 512];
        float2 v3 = X[j + 768];
        int jm = j & (Ns - 1);
        float ang = -6.28318530717958647692f * (float)jm / (float)(4 * Ns);
        float sn, cs;
        __sincosf(ang, &sn, &cs);
        float2 w1 = make_float2(cs, sn);
        float2 w2 = cmulf(w1, w1);
        float2 w3 = cmulf(w2, w1);
        v1 = cmulf(v1, w1);
        v2 = cmulf(v2, w2);
        v3 = cmulf(v3, w3);
        float2 t0 = make_float2(v0.x + v2.x, v0.y + v2.y);
        float2 t1 = make_float2(v0.x - v2.x, v0.y - v2.y);
        float2 t2 = make_float2(v1.x + v3.x, v1.y + v3.y);
        float2 t3 = make_float2(v1.x - v3.x, v1.y - v3.y);
        int idxD = ((j >> s2) << (s2 + 2)) + jm;
        Y[idxD]          = make_float2(t0.x + t2.x, t0.y + t2.y);
        Y[idxD + Ns]     = make_float2(t1.x + t3.y, t1.y - t3.x);
        Y[idxD + 2 * Ns] = make_float2(t0.x - t2.x, t0.y - t2.y);
        Y[idxD + 3 * Ns] = make_float2(t1.x - t3.y, t1.y + t3.x);
        float2* tmp = X; X = Y; Y = tmp;
        __syncthreads();
    }

    #pragma unroll
    for (int jj = 0; jj < 4; jj++) {
        int j = tid + jj * 256;
        float2 z  = X[j];
        float2 zn = X[(L_ - j) & (L_ - 1)];
        float2 Qf = make_float2(0.5f * (z.x + zn.x), 0.5f * (z.y - zn.y));
        float2 Kf = make_float2(0.5f * (z.y + zn.y), -0.5f * (z.x - zn.x));
        float px = Qf.x * Kf.x + Qf.y * Kf.y;
        float py = Qf.y * Kf.x - Qf.x * Kf.y;
        Y[j] = make_float2(px, -py);   // conj(P)
    }
    __syncthreads();
    { float2* tmp = X; X = Y; Y = tmp; }

    #pragma unroll
    for (int stage = 0; stage < 5; stage++) {
        int s2 = 2 * stage;
        int Ns = 1 << s2;
        int j = tid;
        float2 v0 = X[j];
        float2 v1 = X[j + 256];
        float2 v2 = X[j + 512];
        float2 v3 = X[j + 768];
        int jm = j & (Ns - 1);
        float ang = -6.28318530717958647692f * (float)jm / (float)(4 * Ns);
        float sn, cs;
        __sincosf(ang, &sn, &cs);
        float2 w1 = make_float2(cs, sn);
        float2 w2 = cmulf(w1, w1);
        float2 w3 = cmulf(w2, w1);
        v1 = cmulf(v1, w1);
        v2 = cmulf(v2, w2);
        v3 = cmulf(v3, w3);
        float2 t0 = make_float2(v0.x + v2.x, v0.y + v2.y);
        float2 t1 = make_float2(v0.x - v2.x, v0.y - v2.y);
        float2 t2 = make_float2(v1.x + v3.x, v1.y + v3.y);
        float2 t3 = make_float2(v1.x - v3.x, v1.y - v3.y);
        int idxD = ((j >> s2) << (s2 + 2)) + jm;
        Y[idxD]          = make_float2(t0.x + t2.x, t0.y + t2.y);
        Y[idxD + Ns]     = make_float2(t1.x + t3.y, t1.y - t3.x);
        Y[idxD + 2 * Ns] = make_float2(t0.x - t2.x, t0.y - t2.y);
        Y[idxD + 3 * Ns] = make_float2(t1.x - t3.y, t1.y + t3.x);
        float2* tmp = X; X = Y; Y = tmp;
        __syncthreads();
    }

    float* amp = g_amp2_t + bh * L_;
    #pragma unroll
    for (int jj = 0; jj < 4; jj++) {
        int t = tid + jj * 256;
        float ac = X[t].x * (1.0f / (float)L_);
        atomicAdd(amp + t, ac * ac);
    }
}

// Kernel 2: top-35 per (b,h). blockIdx.x = bh + 16*which.
// which=0: consume g_amp2_t then ZERO it (ready for next replay).
// which=1: consume g_amp2_tf; also zero this bh's g_usel slice (mid accumulates).
__global__ void __launch_bounds__(256) topk_kernel() {
    int bh    = blockIdx.x & 15;
    int which = blockIdx.x >> 4;
    int tid = threadIdx.x;
    int lane = tid & 31, wrp = tid >> 5;

    float v[4];
    if (which == 0) {
        #pragma unroll
        for (int jj = 0; jj < 4; jj++) {
            v[jj] = g_amp2_t[bh * L_ + tid + jj * 256];
        }
        #pragma unroll
        for (int jj = 0; jj < 4; jj++)
            g_amp2_t[bh * L_ + tid + jj * 256] = 0.f;    // reset for next replay
    } else {
        #pragma unroll
        for (int jj = 0; jj < 4; jj++)
            v[jj] = g_amp2_tf[bh * L_ + tid + jj * 256];
        // zero this bh's g_usel slice (71*64 = 4544 floats) before mid accumulates
        float* us = g_usel + (size_t)bh * 71 * E_;
        for (int idx = tid; idx < 71 * E_; idx += 256) us[idx] = 0.f;
    }

    __shared__ float sv[8];
    __shared__ int   si[8];

    for (int iter = 0; iter < NT_; iter++) {
        float best = v[0];
        int   bi   = tid;
        #pragma unroll
        for (int jj = 1; jj < 4; jj++) {
            if (v[jj] > best) { best = v[jj]; bi = tid + jj * 256; }
        }
        #pragma unroll
        for (int off = 16; off > 0; off >>= 1) {
            float ov = __shfl_down_sync(0xffffffffu, best, off);
            int   oi = __shfl_down_sync(0xffffffffu, bi,   off);
            if (ov > best || (ov == best && oi < bi)) { best = ov; bi = oi; }
        }
        if (lane == 0) { sv[wrp] = best; si[wrp] = bi; }
        __syncthreads();
        float wv = sv[0]; int wi = si[0];
        #pragma unroll
        for (int w = 1; w < 8; w++) {
            if (sv[w] > wv || (sv[w] == wv && si[w] < wi)) { wv = sv[w]; wi = si[w]; }
        }
        if (tid == 0) g_selidx[bh * NS_ + which * NT_ + iter] = wi;
        if ((wi & 255) == tid) v[wi >> 8] = -1.0f;
        __syncthreads();
    }
}

// Kernel 3: usel-role and scores-role blocks in ONE launch so the two
// independent workloads overlap across SMs.
//  blockIdx.x <  32 : usel role, m-chunk 32 (R10-proven): usel[bh][i][d]
//                     += sum_m W[m,c_i]*V[b,m,h,d]; row 70 uses bias.
//  blockIdx.x >= 32 : scores role, l-tile 32: g_scores[bh][i][l].
__global__ void __launch_bounds__(512) mid_kernel(const float* __restrict__ W,
                                                  const float* __restrict__ bias,
                                                  const float* __restrict__ V,
                                                  const float* __restrict__ tfq,
                                                  const float* __restrict__ q,
                                                  const float* __restrict__ kk) {
    __shared__ float sbuf[4512];
    int bh = blockIdx.y, b = bh >> 3, h = bh & 7;
    int tid = threadIdx.x;

    if (blockIdx.x < 32) {
        // ---------------- usel role ----------------
        float* ws = sbuf;                 // [71][32]
        float* vs = sbuf + 71 * 32;       // [32][64]
        int*   cs_ = (int*)(sbuf + 71 * 32 + 32 * 64);   // [70]
        int m0 = blockIdx.x * 32;

        if (tid < NS_) {
            cs_[tid] = g_selidx[bh * NS_ + tid] + ((tid >= NT_) ? L_ : 0);
        }
        {
            const float4* vsrc = (const float4*)(V + (((size_t)(b * L_ + m0) * H_) + h) * E_);
            int mm = tid >> 4, c4 = tid & 15;
            ((float4*)vs)[tid] = vsrc[(size_t)mm * 128 + c4];
        }
        __syncthreads();

        for (int idx = tid; idx < 71 * 32; idx += 512) {
            int i = idx >> 5, mm = idx & 31;
            float v;
            if (i < NS_) {
                v = __ldg(&W[(size_t)(m0 + mm) * (2 * L_) + cs_[i]]);
            } else {
                v = bias[m0 + mm];
            }
            ws[i * 32 + mm] = v;
        }
        __syncthreads();

        int d = tid & 63, ig = tid >> 6;   // 8 i-groups
        float acc[9];
        #pragma unroll
        for (int kk2 = 0; kk2 < 9; kk2++) acc[kk2] = 0.f;

        #pragma unroll 4
        for (int mm = 0; mm < 32; mm++) {
            float v = vs[mm * 64 + d];
            #pragma unroll
            for (int kk2 = 0; kk2 < 9; kk2++) {
                int i = ig + kk2 * 8;
                if (i < 71) acc[kk2] += ws[i * 32 + mm] * v;
            }
        }
        #pragma unroll
        for (int kk2 = 0; kk2 < 9; kk2++) {
            int i = ig + kk2 * 8;
            if (i < 71) atomicAdd(&g_usel[(size_t)(bh * 71 + i) * E_ + d], acc[kk2]);
        }
    } else {
        // ---------------- scores role ----------------
        float* qsel = sbuf;               // [70][64]
        int lbase = (blockIdx.x - 32) * 32;

        for (int idx = tid; idx < NS_ * E_; idx += 512) {
            int i = idx >> 6, e = idx & 63;
            int src = g_selidx[bh * NS_ + i];
            const float* sp = (i < NT_) ? q : tfq;
            qsel[idx] = sp[(((size_t)(b * L_ + src) * H_) + h) * E_ + e];
        }
        __syncthreads();

        int g = tid >> 5;                 // 16 groups of 32
        int lane = tid & 31;
        int half = g >> 3;                // 0: vs keys, 1: vs tf_queries
        int iseg = g & 7;                 // strided i = iseg + 8*t
        int cnt = (iseg < 3) ? 5 : 4;     // 3*5 + 5*4 = 35
        int l = lbase + lane;

        const float4* row = (const float4*)(((half == 0) ? kk : tfq)
                            + (((size_t)(b * L_ + l) * H_) + h) * E_);
        float part[5];
        #pragma unroll
        for (int t = 0; t < 5; t++) part[t] = 0.f;

        #pragma unroll
        for (int jh = 0; jh < 2; jh++) {
            float4 r[8];
            #pragma unroll
            for (int j = 0; j < 8; j++) r[j] = row[jh * 8 + j];

            for (int t = 0; t < cnt; t++) {
                int i = iseg + 8 * t;
                const float4* qr = (const float4*)&qsel[(half * NT_ + i) * E_ + jh * 32];
                float s0 = 0.f, s1 = 0.f;
                #pragma unroll
                for (int j = 0; j < 4; j++) {
                    float4 qa = qr[j];
                    float4 qb = qr[j + 4];
                    s0 += qa.x * r[j].x + qa.y * r[j].y + qa.z * r[j].z + qa.w * r[j].w;
                    s1 += qb.x * r[j + 4].x + qb.y * r[j + 4].y + qb.z * r[j + 4].z + qb.w * r[j + 4].w;
                }
                part[t] += s0 + s1;
            }
        }
        for (int t = 0; t < cnt; t++) {
            int i = iseg + 8 * t;
            g_scores[(size_t)(bh * NS_ + half * NT_ + i) * L_ + l] = part[t] * SCALE_;
        }
    }
}

// Kernel 4: softmax over 70 scores + combine with g_usel. One block = 32 l of
// one (b,h), 128 threads. Scores staged in smem (coalesced loads), then 8
// groups x 4 l, lane16 covers d as float4.
__global__ void __launch_bounds__(128) final_kernel(float* __restrict__ out) {
    __shared__ float s[NS_][32];
    int bh = blockIdx.y, b = bh >> 3, h = bh & 7;
    int tid = threadIdx.x;
    int lane16 = tid & 15;
    int g = tid >> 4;                     // 8 groups
    int lbase = blockIdx.x * 32;

    for (int idx = tid; idx < NS_ * 32; idx += 128) {
        int i = idx >> 5, lt = idx & 31;
        s[i][lt] = g_scores[(size_t)(bh * NS_ + i) * L_ + lbase + lt];
    }
    __syncthreads();

    const float* us = g_usel + (size_t)bh * 71 * E_;
    float4 bb = ((const float4*)(us + NS_ * E_))[lane16];

    #pragma unroll
    for (int ll = 0; ll < 4; ll++) {
        int lt = g * 4 + ll;
        int l = lbase + lt;

        float mx = -1e30f;
        #pragma unroll
        for (int i = 0; i < NS_; i++) mx = fmaxf(mx, s[i][lt]);

        float4 acc = make_float4(0.f, 0.f, 0.f, 0.f);
        float ssum = 0.f;
        for (int i = 0; i < NS_; i++) {
            float p = __expf(s[i][lt] - mx);
            ssum += p;
            float4 u = ((const float4*)(us + i * E_))[lane16];
            acc.x += p * u.x; acc.y += p * u.y;
            acc.z += p * u.z; acc.w += p * u.w;
        }
        float inv = 1.f / ssum;
        float4* op = (float4*)(out + (((size_t)(b * L_ + l) * H_) + h) * E_) + lane16;
        *op = make_float4(acc.x * inv + bb.x, acc.y * inv + bb.y,
                          acc.z * inv + bb.z, acc.w * inv + bb.w);
    }
}

extern "C" void kernel_launch(void* const* d_in, const int* in_sizes, int n_in,
                              void* d_out, int out_size) {
    const float* tfq  = (const float*)d_in[0];
    const float* q    = (const float*)d_in[1];
    const float* k    = (const float*)d_in[2];
    const float* v    = (const float*)d_in[3];
    // d_in[4] = mask (unused)
    const float* W    = (const float*)d_in[5];
    const float* bias = (const float*)d_in[6];
    float* out = (float*)d_out;

    corr_tf_kernel<<<1040, 256>>>(q, k, tfq);
    topk_kernel<<<32, 256>>>();
    mid_kernel<<<dim3(64, BH_), 512>>>(W, bias, v, tfq, q, k);
    final_kernel<<<dim3(32, BH_), 128>>>(out);
}

// round 12
// speedup vs baseline: 2.2743x; 2.2743x over previous
#include <cuda_runtime.h>
#include <math.h>

// Problem constants: B=2, L=1024, H=8, E=64, n_top=35 (5*ceil(ln 1024))
#define B_  2
#define L_  1024
#define H_  8
#define E_  64
#define BH_ 16
#define NT_ 35      // top-k per half
#define NS_ 70      // total selected columns
#define SCALE_ 0.125f

// -------- static scratch (no allocations allowed) --------
// Invariant: g_amp2_t and g_usel are ZERO at kernel_launch entry (zero-init at
// module load; topk_kernel re-establishes the invariant every run).
__device__ float g_amp2_t[BH_ * L_];            // corr amplitudes^2 (atomic accum)
__device__ float g_amp2_tf[BH_ * L_];           // tf-query norms^2 (overwritten)
__device__ int   g_selidx[BH_ * NS_];           // [0..34]=idx_t, [35..69]=idx_tf
__device__ float g_usel[BH_ * 71 * E_];         // row 70 = bias row bv

__device__ __forceinline__ float2 cmulf(float2 a, float2 b) {
    return make_float2(a.x * b.x - a.y * b.y, a.x * b.y + a.y * b.x);
}

// Kernel 1: blocks [0,1024): FFT circular correlation per channel (b,h,e),
// atomic-accumulating ac^2 into g_amp2_t. blocks [1024,1040): tf-query row
// norms^2 per (b,h), direct store into g_amp2_tf.
__global__ void __launch_bounds__(256) corr_tf_kernel(const float* __restrict__ q,
                                                      const float* __restrict__ k,
                                                      const float* __restrict__ tfq) {
    __shared__ float2 bufA[L_];
    __shared__ float2 bufB[L_];
    int tid = threadIdx.x;

    if (blockIdx.x >= 1024) {
        // ---- tf-norm role ----
        int bh = blockIdx.x - 1024;
        int b = bh >> 3, h = bh & 7;
        #pragma unroll
        for (int jj = 0; jj < 4; jj++) {
            int l = tid + jj * 256;
            const float4* p = (const float4*)(tfq + (((size_t)(b * L_ + l) * H_ + h) * E_));
            float s = 0.f;
            #pragma unroll
            for (int j = 0; j < 16; j++) {
                float4 x = p[j];
                s += x.x * x.x + x.y * x.y + x.z * x.z + x.w * x.w;
            }
            g_amp2_tf[bh * L_ + l] = s;
        }
        return;
    }

    // ---- corr role ----
    int ch = blockIdx.x;            // b*512 + h*64 + e
    int e  = ch & 63;
    int bh = ch >> 6;
    int h  = bh & 7;
    int b  = bh >> 3;

    size_t base = (size_t)b * (L_ * H_ * E_) + (size_t)h * E_ + e;
    #pragma unroll
    for (int jj = 0; jj < 4; jj++) {
        int l = tid + jj * 256;
        bufA[l] = make_float2(q[base + (size_t)l * (H_ * E_)],
                              k[base + (size_t)l * (H_ * E_)]);
    }
    __syncthreads();

    float2* X = bufA;
    float2* Y = bufB;

    #pragma unroll
    for (int stage = 0; stage < 5; stage++) {
        int s2 = 2 * stage;
        int Ns = 1 << s2;
        int j = tid;
        float2 v0 = X[j];
        float2 v1 = X[j + 256];
        float2 v2 = X[j + 512];
        float2 v3 = X[j + 768];
        int jm = j & (Ns - 1);
        float ang = -6.28318530717958647692f * (float)jm / (float)(4 * Ns);
        float sn, cs;
        __sincosf(ang, &sn, &cs);
        float2 w1 = make_float2(cs, sn);
        float2 w2 = cmulf(w1, w1);
        float2 w3 = cmulf(w2, w1);
        v1 = cmulf(v1, w1);
        v2 = cmulf(v2, w2);
        v3 = cmulf(v3, w3);
        float2 t0 = make_float2(v0.x + v2.x, v0.y + v2.y);
        float2 t1 = make_float2(v0.x - v2.x, v0.y - v2.y);
        float2 t2 = make_float2(v1.x + v3.x, v1.y + v3.y);
        float2 t3 = make_float2(v1.x - v3.x, v1.y - v3.y);
        int idxD = ((j >> s2) << (s2 + 2)) + jm;
        Y[idxD]          = make_float2(t0.x + t2.x, t0.y + t2.y);
        Y[idxD + Ns]     = make_float2(t1.x + t3.y, t1.y - t3.x);
        Y[idxD + 2 * Ns] = make_float2(t0.x - t2.x, t0.y - t2.y);
        Y[idxD + 3 * Ns] = make_float2(t1.x - t3.y, t1.y + t3.x);
        float2* tmp = X; X = Y; Y = tmp;
        __syncthreads();
    }

    #pragma unroll
    for (int jj = 0; jj < 4; jj++) {
        int j = tid + jj * 256;
        float2 z  = X[j];
        float2 zn = X[(L_ - j) & (L_ - 1)];
        float2 Qf = make_float2(0.5f * (z.x + zn.x), 0.5f * (z.y - zn.y));
        float2 Kf = make_float2(0.5f * (z.y + zn.y), -0.5f * (z.x - zn.x));
        float px = Qf.x * Kf.x + Qf.y * Kf.y;
        float py = Qf.y * Kf.x - Qf.x * Kf.y;
        Y[j] = make_float2(px, -py);   // conj(P)
    }
    __syncthreads();
    { float2* tmp = X; X = Y; Y = tmp; }

    #pragma unroll
    for (int stage = 0; stage < 5; stage++) {
        int s2 = 2 * stage;
        int Ns = 1 << s2;
        int j = tid;
        float2 v0 = X[j];
        float2 v1 = X[j + 256];
        float2 v2 = X[j + 512];
        float2 v3 = X[j + 768];
        int jm = j & (Ns - 1);
        float ang = -6.28318530717958647692f * (float)jm / (float)(4 * Ns);
        float sn, cs;
        __sincosf(ang, &sn, &cs);
        float2 w1 = make_float2(cs, sn);
        float2 w2 = cmulf(w1, w1);
        float2 w3 = cmulf(w2, w1);
        v1 = cmulf(v1, w1);
        v2 = cmulf(v2, w2);
        v3 = cmulf(v3, w3);
        float2 t0 = make_float2(v0.x + v2.x, v0.y + v2.y);
        float2 t1 = make_float2(v0.x - v2.x, v0.y - v2.y);
        float2 t2 = make_float2(v1.x + v3.x, v1.y + v3.y);
        float2 t3 = make_float2(v1.x - v3.x, v1.y - v3.y);
        int idxD = ((j >> s2) << (s2 + 2)) + jm;
        Y[idxD]          = make_float2(t0.x + t2.x, t0.y + t2.y);
        Y[idxD + Ns]     = make_float2(t1.x + t3.y, t1.y - t3.x);
        Y[idxD + 2 * Ns] = make_float2(t0.x - t2.x, t0.y - t2.y);
        Y[idxD + 3 * Ns] = make_float2(t1.x - t3.y, t1.y + t3.x);
        float2* tmp = X; X = Y; Y = tmp;
        __syncthreads();
    }

    float* amp = g_amp2_t + bh * L_;
    #pragma unroll
    for (int jj = 0; jj < 4; jj++) {
        int t = tid + jj * 256;
        float ac = X[t].x * (1.0f / (float)L_);
        atomicAdd(amp + t, ac * ac);
    }
}

// Kernel 2: top-35 per (b,h). blockIdx.x = bh + 16*which.
// which=0: consume g_amp2_t then ZERO it (invariant for next replay).
// which=1: consume g_amp2_tf; also zero this bh's g_usel slice before usel accumulates.
__global__ void __launch_bounds__(256) topk_kernel() {
    int bh    = blockIdx.x & 15;
    int which = blockIdx.x >> 4;
    int tid = threadIdx.x;
    int lane = tid & 31, wrp = tid >> 5;

    float v[4];
    if (which == 0) {
        #pragma unroll
        for (int jj = 0; jj < 4; jj++)
            v[jj] = g_amp2_t[bh * L_ + tid + jj * 256];
        #pragma unroll
        for (int jj = 0; jj < 4; jj++)
            g_amp2_t[bh * L_ + tid + jj * 256] = 0.f;    // reset for next replay
    } else {
        #pragma unroll
        for (int jj = 0; jj < 4; jj++)
            v[jj] = g_amp2_tf[bh * L_ + tid + jj * 256];
        float* us = g_usel + (size_t)bh * 71 * E_;
        for (int idx = tid; idx < 71 * E_; idx += 256) us[idx] = 0.f;
    }

    __shared__ float sv[8];
    __shared__ int   si[8];

    for (int iter = 0; iter < NT_; iter++) {
        float best = v[0];
        int   bi   = tid;
        #pragma unroll
        for (int jj = 1; jj < 4; jj++) {
            if (v[jj] > best) { best = v[jj]; bi = tid + jj * 256; }
        }
        #pragma unroll
        for (int off = 16; off > 0; off >>= 1) {
            float ov = __shfl_down_sync(0xffffffffu, best, off);
            int   oi = __shfl_down_sync(0xffffffffu, bi,   off);
            if (ov > best || (ov == best && oi < bi)) { best = ov; bi = oi; }
        }
        if (lane == 0) { sv[wrp] = best; si[wrp] = bi; }
        __syncthreads();
        float wv = sv[0]; int wi = si[0];
        #pragma unroll
        for (int w = 1; w < 8; w++) {
            if (sv[w] > wv || (sv[w] == wv && si[w] < wi)) { wv = sv[w]; wi = si[w]; }
        }
        if (tid == 0) g_selidx[bh * NS_ + which * NT_ + iter] = wi;
        if ((wi & 255) == tid) v[wi >> 8] = -1.0f;
        __syncthreads();
    }
}

// Kernel 3 (R10-proven, 17.6us): usel[bh][i][d] += sum_m W[m,c_i]*V[b,m,h,d];
// row 70 uses bias. m-chunk = 32 rows, grid (32, 16), 512 threads.
__global__ void __launch_bounds__(512) usel_kernel(const float* __restrict__ W,
                                                   const float* __restrict__ bias,
                                                   const float* __restrict__ V) {
    int bh = blockIdx.y, b = bh >> 3, h = bh & 7;
    int m0 = blockIdx.x * 32;
    __shared__ float ws[71][32];
    __shared__ float vs[32][64];
    __shared__ int   cs_[NS_];
    int tid = threadIdx.x;

    if (tid < NS_) {
        cs_[tid] = g_selidx[bh * NS_ + tid] + ((tid >= NT_) ? L_ : 0);
    }
    {
        const float4* vsrc = (const float4*)(V + (((size_t)(b * L_ + m0) * H_) + h) * E_);
        int mm = tid >> 4, c4 = tid & 15;
        ((float4*)vs)[tid] = vsrc[(size_t)mm * 128 + c4];
    }
    __syncthreads();

    for (int idx = tid; idx < 71 * 32; idx += 512) {
        int i = idx >> 5, mm = idx & 31;
        float v;
        if (i < NS_) {
            v = __ldg(&W[(size_t)(m0 + mm) * (2 * L_) + cs_[i]]);
        } else {
            v = bias[m0 + mm];
        }
        ws[i][mm] = v;
    }
    __syncthreads();

    int d = tid & 63, ig = tid >> 6;   // 8 i-groups
    float acc[9];
    #pragma unroll
    for (int kk2 = 0; kk2 < 9; kk2++) acc[kk2] = 0.f;

    #pragma unroll 4
    for (int mm = 0; mm < 32; mm++) {
        float v = vs[mm][d];
        #pragma unroll
        for (int kk2 = 0; kk2 < 9; kk2++) {
            int i = ig + kk2 * 8;
            if (i < 71) acc[kk2] += ws[i][mm] * v;
        }
    }
    #pragma unroll
    for (int kk2 = 0; kk2 < 9; kk2++) {
        int i = ig + kk2 * 8;
        if (i < 71) atomicAdd(&g_usel[(size_t)(bh * 71 + i) * E_ + d], acc[kk2]);
    }
}

// Kernel 4 (R10-proven): fused scores + softmax + combine.
// One block = 16 l of one (b,h), 128 threads, grid (64, 16).
__global__ void __launch_bounds__(128) fused_kernel(const float* __restrict__ tfq,
                                                    const float* __restrict__ q,
                                                    const float* __restrict__ kk,
                                                    float* __restrict__ out) {
    int bh = blockIdx.y, b = bh >> 3, h = bh & 7;
    int tid = threadIdx.x;
    int lane16 = tid & 15;
    int g = tid >> 4;               // 8 groups of 16

    __shared__ float qsel[NS_ * E_];    // selected query rows
    __shared__ float s[NS_][16];        // scores for this l-tile

    for (int idx = tid; idx < NS_ * E_; idx += 128) {
        int i = idx >> 6, e = idx & 63;
        int src = g_selidx[bh * NS_ + i];
        const float* sp = (i < NT_) ? q : tfq;
        qsel[idx] = sp[(((size_t)(b * L_ + src) * H_) + h) * E_ + e];
    }
    __syncthreads();

    // ---- phase 1: scores ----
    {
        int half = g >> 2;              // 0: vs keys, 1: vs tf_queries
        int iseg = g & 3;
        int i0 = iseg * 9;
        int cnt = (i0 + 9 < NT_) ? 9 : (NT_ - i0);   // 9,9,9,8
        int l = blockIdx.x * 16 + lane16;

        const float4* row = (const float4*)(((half == 0) ? kk : tfq)
                            + (((size_t)(b * L_ + l) * H_) + h) * E_);
        float part[9];
        #pragma unroll
        for (int ii = 0; ii < 9; ii++) part[ii] = 0.f;

        #pragma unroll
        for (int jh = 0; jh < 2; jh++) {
            float4 r[8];
            #pragma unroll
            for (int j = 0; j < 8; j++) r[j] = row[jh * 8 + j];

            for (int ii = 0; ii < cnt; ii++) {
                const float4* qr = (const float4*)&qsel[(half * NT_ + i0 + ii) * E_ + jh * 32];
                float s0 = 0.f, s1 = 0.f;
                #pragma unroll
                for (int j = 0; j < 4; j++) {
                    float4 qa = qr[j];
                    float4 qb = qr[j + 4];
                    s0 += qa.x * r[j].x + qa.y * r[j].y + qa.z * r[j].z + qa.w * r[j].w;
                    s1 += qb.x * r[j + 4].x + qb.y * r[j + 4].y + qb.z * r[j + 4].z + qb.w * r[j + 4].w;
                }
                part[ii] += s0 + s1;
            }
        }
        for (int ii = 0; ii < cnt; ii++)
            s[half * NT_ + i0 + ii][lane16] = part[ii] * SCALE_;
    }
    __syncthreads();

    // ---- phase 2: softmax + combine (8 groups x 2 l; lane16 -> d) ----
    {
        const float* us = g_usel + (size_t)bh * 71 * E_;
        const float4* bv = (const float4*)(us + NS_ * E_) + lane16;
        float4 bb = *bv;

        #pragma unroll
        for (int ll = 0; ll < 2; ll++) {
            int lt = g * 2 + ll;            // 0..15 within tile
            int l = blockIdx.x * 16 + lt;

            float mx = -1e30f;
            #pragma unroll
            for (int i = 0; i < NS_; i++) mx = fmaxf(mx, s[i][lt]);

            float4 acc = make_float4(0.f, 0.f, 0.f, 0.f);
            float ssum = 0.f;

            for (int i = 0; i < NS_; i++) {
                float p = __expf(s[i][lt] - mx);
                ssum += p;
                float4 u = ((const float4*)(us + i * E_))[lane16];
                acc.x += p * u.x; acc.y += p * u.y;
                acc.z += p * u.z; acc.w += p * u.w;
            }
            float inv = 1.f / ssum;
            float4* op = (float4*)(out + (((size_t)(b * L_ + l) * H_) + h) * E_) + lane16;
            *op = make_float4(acc.x * inv + bb.x, acc.y * inv + bb.y,
                              acc.z * inv + bb.z, acc.w * inv + bb.w);
        }
    }
}

extern "C" void kernel_launch(void* const* d_in, const int* in_sizes, int n_in,
                              void* d_out, int out_size) {
    const float* tfq  = (const float*)d_in[0];
    const float* q    = (const float*)d_in[1];
    const float* k    = (const float*)d_in[2];
    const float* v    = (const float*)d_in[3];
    // d_in[4] = mask (unused)
    const float* W    = (const float*)d_in[5];
    const float* bias = (const float*)d_in[6];
    float* out = (float*)d_out;

    corr_tf_kernel<<<1040, 256>>>(q, k, tfq);
    topk_kernel<<<32, 256>>>();
    usel_kernel<<<dim3(32, BH_), 512>>>(W, bias, v);
    fused_kernel<<<dim3(64, BH_), 128>>>(tfq, q, k, out);
}

// round 13
// speedup vs baseline: 2.3898x; 1.0508x over previous
#include <cuda_runtime.h>
#include <math.h>

// Problem constants: B=2, L=1024, H=8, E=64, n_top=35 (5*ceil(ln 1024))
#define B_  2
#define L_  1024
#define H_  8
#define E_  64
#define BH_ 16
#define NT_ 35      // top-k per half
#define NS_ 70      // total selected columns
#define SCALE_ 0.125f

// -------- static scratch (no allocations allowed) --------
// Invariant: g_amp2_t and g_usel are ZERO at kernel_launch entry (zero-init at
// module load; topk_kernel re-establishes the invariant every run).
__device__ float g_amp2_t[BH_ * L_];            // corr amplitudes^2 (atomic accum)
__device__ float g_amp2_tf[BH_ * L_];           // tf-query norms^2 (overwritten)
__device__ int   g_selidx[BH_ * NS_];           // [0..34]=idx_t, [35..69]=idx_tf
__device__ float g_usel[BH_ * 71 * E_];         // row 70 = bias row bv

__device__ __forceinline__ float2 cmulf(float2 a, float2 b) {
    return make_float2(a.x * b.x - a.y * b.y, a.x * b.y + a.y * b.x);
}

// Kernel 1: blocks [0,1024): FFT circular correlation per channel (b,h,e),
// atomic-accumulating ac^2 into g_amp2_t. blocks [1024,1040): tf-query row
// norms^2 per (b,h), direct store into g_amp2_tf.
__global__ void __launch_bounds__(256) corr_tf_kernel(const float* __restrict__ q,
                                                      const float* __restrict__ k,
                                                      const float* __restrict__ tfq) {
    __shared__ float2 bufA[L_];
    __shared__ float2 bufB[L_];
    int tid = threadIdx.x;

    if (blockIdx.x >= 1024) {
        // ---- tf-norm role ----
        int bh = blockIdx.x - 1024;
        int b = bh >> 3, h = bh & 7;
        #pragma unroll
        for (int jj = 0; jj < 4; jj++) {
            int l = tid + jj * 256;
            const float4* p = (const float4*)(tfq + (((size_t)(b * L_ + l) * H_ + h) * E_));
            float s = 0.f;
            #pragma unroll
            for (int j = 0; j < 16; j++) {
                float4 x = p[j];
                s += x.x * x.x + x.y * x.y + x.z * x.z + x.w * x.w;
            }
            g_amp2_tf[bh * L_ + l] = s;
        }
        return;
    }

    // ---- corr role ----
    int ch = blockIdx.x;            // b*512 + h*64 + e
    int e  = ch & 63;
    int bh = ch >> 6;
    int h  = bh & 7;
    int b  = bh >> 3;

    size_t base = (size_t)b * (L_ * H_ * E_) + (size_t)h * E_ + e;
    #pragma unroll
    for (int jj = 0; jj < 4; jj++) {
        int l = tid + jj * 256;
        bufA[l] = make_float2(q[base + (size_t)l * (H_ * E_)],
                              k[base + (size_t)l * (H_ * E_)]);
    }
    __syncthreads();

    float2* X = bufA;
    float2* Y = bufB;

    #pragma unroll
    for (int stage = 0; stage < 5; stage++) {
        int s2 = 2 * stage;
        int Ns = 1 << s2;
        int j = tid;
        float2 v0 = X[j];
        float2 v1 = X[j + 256];
        float2 v2 = X[j + 512];
        float2 v3 = X[j + 768];
        int jm = j & (Ns - 1);
        float ang = -6.28318530717958647692f * (float)jm / (float)(4 * Ns);
        float sn, cs;
        __sincosf(ang, &sn, &cs);
        float2 w1 = make_float2(cs, sn);
        float2 w2 = cmulf(w1, w1);
        float2 w3 = cmulf(w2, w1);
        v1 = cmulf(v1, w1);
        v2 = cmulf(v2, w2);
        v3 = cmulf(v3, w3);
        float2 t0 = make_float2(v0.x + v2.x, v0.y + v2.y);
        float2 t1 = make_float2(v0.x - v2.x, v0.y - v2.y);
        float2 t2 = make_float2(v1.x + v3.x, v1.y + v3.y);
        float2 t3 = make_float2(v1.x - v3.x, v1.y - v3.y);
        int idxD = ((j >> s2) << (s2 + 2)) + jm;
        Y[idxD]          = make_float2(t0.x + t2.x, t0.y + t2.y);
        Y[idxD + Ns]     = make_float2(t1.x + t3.y, t1.y - t3.x);
        Y[idxD + 2 * Ns] = make_float2(t0.x - t2.x, t0.y - t2.y);
        Y[idxD + 3 * Ns] = make_float2(t1.x - t3.y, t1.y + t3.x);
        float2* tmp = X; X = Y; Y = tmp;
        __syncthreads();
    }

    #pragma unroll
    for (int jj = 0; jj < 4; jj++) {
        int j = tid + jj * 256;
        float2 z  = X[j];
        float2 zn = X[(L_ - j) & (L_ - 1)];
        float2 Qf = make_float2(0.5f * (z.x + zn.x), 0.5f * (z.y - zn.y));
        float2 Kf = make_float2(0.5f * (z.y + zn.y), -0.5f * (z.x - zn.x));
        float px = Qf.x * Kf.x + Qf.y * Kf.y;
        float py = Qf.y * Kf.x - Qf.x * Kf.y;
        Y[j] = make_float2(px, -py);   // conj(P)
    }
    __syncthreads();
    { float2* tmp = X; X = Y; Y = tmp; }

    #pragma unroll
    for (int stage = 0; stage < 5; stage++) {
        int s2 = 2 * stage;
        int Ns = 1 << s2;
        int j = tid;
        float2 v0 = X[j];
        float2 v1 = X[j + 256];
        float2 v2 = X[j + 512];
        float2 v3 = X[j + 768];
        int jm = j & (Ns - 1);
        float ang = -6.28318530717958647692f * (float)jm / (float)(4 * Ns);
        float sn, cs;
        __sincosf(ang, &sn, &cs);
        float2 w1 = make_float2(cs, sn);
        float2 w2 = cmulf(w1, w1);
        float2 w3 = cmulf(w2, w1);
        v1 = cmulf(v1, w1);
        v2 = cmulf(v2, w2);
        v3 = cmulf(v3, w3);
        float2 t0 = make_float2(v0.x + v2.x, v0.y + v2.y);
        float2 t1 = make_float2(v0.x - v2.x, v0.y - v2.y);
        float2 t2 = make_float2(v1.x + v3.x, v1.y + v3.y);
        float2 t3 = make_float2(v1.x - v3.x, v1.y - v3.y);
        int idxD = ((j >> s2) << (s2 + 2)) + jm;
        Y[idxD]          = make_float2(t0.x + t2.x, t0.y + t2.y);
        Y[idxD + Ns]     = make_float2(t1.x + t3.y, t1.y - t3.x);
        Y[idxD + 2 * Ns] = make_float2(t0.x - t2.x, t0.y - t2.y);
        Y[idxD + 3 * Ns] = make_float2(t1.x - t3.y, t1.y + t3.x);
        float2* tmp = X; X = Y; Y = tmp;
        __syncthreads();
    }

    float* amp = g_amp2_t + bh * L_;
    #pragma unroll
    for (int jj = 0; jj < 4; jj++) {
        int t = tid + jj * 256;
        float ac = X[t].x * (1.0f / (float)L_);
        atomicAdd(amp + t, ac * ac);
    }
}

// Kernel 2: top-35 per (b,h). blockIdx.x = bh + 16*which.
// which=0: consume g_amp2_t then ZERO it (invariant for next replay).
// which=1: consume g_amp2_tf; also zero this bh's g_usel slice before usel accumulates.
__global__ void __launch_bounds__(256) topk_kernel() {
    int bh    = blockIdx.x & 15;
    int which = blockIdx.x >> 4;
    int tid = threadIdx.x;
    int lane = tid & 31, wrp = tid >> 5;

    float v[4];
    if (which == 0) {
        #pragma unroll
        for (int jj = 0; jj < 4; jj++)
            v[jj] = g_amp2_t[bh * L_ + tid + jj * 256];
        #pragma unroll
        for (int jj = 0; jj < 4; jj++)
            g_amp2_t[bh * L_ + tid + jj * 256] = 0.f;    // reset for next replay
    } else {
        #pragma unroll
        for (int jj = 0; jj < 4; jj++)
            v[jj] = g_amp2_tf[bh * L_ + tid + jj * 256];
        float* us = g_usel + (size_t)bh * 71 * E_;
        for (int idx = tid; idx < 71 * E_; idx += 256) us[idx] = 0.f;
    }

    __shared__ float sv[8];
    __shared__ int   si[8];

    for (int iter = 0; iter < NT_; iter++) {
        float best = v[0];
        int   bi   = tid;
        #pragma unroll
        for (int jj = 1; jj < 4; jj++) {
            if (v[jj] > best) { best = v[jj]; bi = tid + jj * 256; }
        }
        #pragma unroll
        for (int off = 16; off > 0; off >>= 1) {
            float ov = __shfl_down_sync(0xffffffffu, best, off);
            int   oi = __shfl_down_sync(0xffffffffu, bi,   off);
            if (ov > best || (ov == best && oi < bi)) { best = ov; bi = oi; }
        }
        if (lane == 0) { sv[wrp] = best; si[wrp] = bi; }
        __syncthreads();
        float wv = sv[0]; int wi = si[0];
        #pragma unroll
        for (int w = 1; w < 8; w++) {
            if (sv[w] > wv || (sv[w] == wv && si[w] < wi)) { wv = sv[w]; wi = si[w]; }
        }
        if (tid == 0) g_selidx[bh * NS_ + which * NT_ + iter] = wi;
        if ((wi & 255) == tid) v[wi >> 8] = -1.0f;
        __syncthreads();
    }
}

// Kernel 3 (R10-proven, 17.6us): usel[bh][i][d] += sum_m W[m,c_i]*V[b,m,h,d];
// row 70 uses bias. m-chunk = 32 rows, grid (32, 16), 512 threads.
__global__ void __launch_bounds__(512) usel_kernel(const float* __restrict__ W,
                                                   const float* __restrict__ bias,
                                                   const float* __restrict__ V) {
    int bh = blockIdx.y, b = bh >> 3, h = bh & 7;
    int m0 = blockIdx.x * 32;
    __shared__ float ws[71][32];
    __shared__ float vs[32][64];
    __shared__ int   cs_[NS_];
    int tid = threadIdx.x;

    if (tid < NS_) {
        cs_[tid] = g_selidx[bh * NS_ + tid] + ((tid >= NT_) ? L_ : 0);
    }
    {
        const float4* vsrc = (const float4*)(V + (((size_t)(b * L_ + m0) * H_) + h) * E_);
        int mm = tid >> 4, c4 = tid & 15;
        ((float4*)vs)[tid] = vsrc[(size_t)mm * 128 + c4];
    }
    __syncthreads();

    for (int idx = tid; idx < 71 * 32; idx += 512) {
        int i = idx >> 5, mm = idx & 31;
        float v;
        if (i < NS_) {
            v = __ldg(&W[(size_t)(m0 + mm) * (2 * L_) + cs_[i]]);
        } else {
            v = bias[m0 + mm];
        }
        ws[i][mm] = v;
    }
    __syncthreads();

    int d = tid & 63, ig = tid >> 6;   // 8 i-groups
    float acc[9];
    #pragma unroll
    for (int kk2 = 0; kk2 < 9; kk2++) acc[kk2] = 0.f;

    #pragma unroll 4
    for (int mm = 0; mm < 32; mm++) {
        float v = vs[mm][d];
        #pragma unroll
        for (int kk2 = 0; kk2 < 9; kk2++) {
            int i = ig + kk2 * 8;
            if (i < 71) acc[kk2] += ws[i][mm] * v;
        }
    }
    #pragma unroll
    for (int kk2 = 0; kk2 < 9; kk2++) {
        int i = ig + kk2 * 8;
        if (i < 71) atomicAdd(&g_usel[(size_t)(bh * 71 + i) * E_ + d], acc[kk2]);
    }
}

// Kernel 4: fused scores + softmax + combine. One block = 16 l of one (b,h),
// 128 threads, grid (64, 16).
// Phase 1 (unchanged from R10/R12): scores into s[][] using qsel staged in buf.
// Phase 1.5 (NEW): after phase 1, reload the SAME buf with g_usel (71x64,
//   one coalesced 18KB read per block instead of 286KB of per-(i,l) L2 reads).
// Phase 2 (NEW): softmax + combine reading us from smem; each 16-thread group
//   handles its 2 l's in one pass so each u float4 smem read serves both.
__global__ void __launch_bounds__(128) fused_kernel(const float* __restrict__ tfq,
                                                    const float* __restrict__ q,
                                                    const float* __restrict__ kk,
                                                    float* __restrict__ out) {
    int bh = blockIdx.y, b = bh >> 3, h = bh & 7;
    int tid = threadIdx.x;
    int lane16 = tid & 15;
    int g = tid >> 4;               // 8 groups of 16

    __shared__ float buf[71 * E_];      // qsel (phase 1) then usel+bias (phase 2)
    __shared__ float s[NS_][16];        // scores for this l-tile

    for (int idx = tid; idx < NS_ * E_; idx += 128) {
        int i = idx >> 6, e = idx & 63;
        int src = g_selidx[bh * NS_ + i];
        const float* sp = (i < NT_) ? q : tfq;
        buf[idx] = sp[(((size_t)(b * L_ + src) * H_) + h) * E_ + e];
    }
    __syncthreads();

    // ---- phase 1: scores ----
    {
        int half = g >> 2;              // 0: vs keys, 1: vs tf_queries
        int iseg = g & 3;
        int i0 = iseg * 9;
        int cnt = (i0 + 9 < NT_) ? 9 : (NT_ - i0);   // 9,9,9,8
        int l = blockIdx.x * 16 + lane16;

        const float4* row = (const float4*)(((half == 0) ? kk : tfq)
                            + (((size_t)(b * L_ + l) * H_) + h) * E_);
        float part[9];
        #pragma unroll
        for (int ii = 0; ii < 9; ii++) part[ii] = 0.f;

        #pragma unroll
        for (int jh = 0; jh < 2; jh++) {
            float4 r[8];
            #pragma unroll
            for (int j = 0; j < 8; j++) r[j] = row[jh * 8 + j];

            for (int ii = 0; ii < cnt; ii++) {
                const float4* qr = (const float4*)&buf[(half * NT_ + i0 + ii) * E_ + jh * 32];
                float s0 = 0.f, s1 = 0.f;
                #pragma unroll
                for (int j = 0; j < 4; j++) {
                    float4 qa = qr[j];
                    float4 qb = qr[j + 4];
                    s0 += qa.x * r[j].x + qa.y * r[j].y + qa.z * r[j].z + qa.w * r[j].w;
                    s1 += qb.x * r[j + 4].x + qb.y * r[j + 4].y + qb.z * r[j + 4].z + qb.w * r[j + 4].w;
                }
                part[ii] += s0 + s1;
            }
        }
        for (int ii = 0; ii < cnt; ii++)
            s[half * NT_ + i0 + ii][lane16] = part[ii] * SCALE_;
    }
    __syncthreads();   // all phase-1 reads of buf complete

    // ---- phase 1.5: stage usel (+bias row) into buf, coalesced ----
    {
        const float4* us4 = (const float4*)(g_usel + (size_t)bh * 71 * E_);
        float4* b4 = (float4*)buf;
        for (int idx = tid; idx < 71 * (E_ / 4); idx += 128)
            b4[idx] = us4[idx];
    }
    __syncthreads();

    // ---- phase 2: softmax + combine (each group: 2 l in one pass) ----
    {
        float4 bb = ((const float4*)&buf[NS_ * E_])[lane16];
        int lt0 = g * 2, lt1 = lt0 + 1;

        float mx0 = -1e30f, mx1 = -1e30f;
        #pragma unroll
        for (int i = 0; i < NS_; i++) {
            mx0 = fmaxf(mx0, s[i][lt0]);
            mx1 = fmaxf(mx1, s[i][lt1]);
        }

        float4 acc0 = make_float4(0.f, 0.f, 0.f, 0.f);
        float4 acc1 = make_float4(0.f, 0.f, 0.f, 0.f);
        float ssum0 = 0.f, ssum1 = 0.f;

        for (int i = 0; i < NS_; i++) {
            float p0 = __expf(s[i][lt0] - mx0);
            float p1 = __expf(s[i][lt1] - mx1);
            ssum0 += p0; ssum1 += p1;
            float4 u = ((const float4*)&buf[i * E_])[lane16];
            acc0.x += p0 * u.x; acc0.y += p0 * u.y;
            acc0.z += p0 * u.z; acc0.w += p0 * u.w;
            acc1.x += p1 * u.x; acc1.y += p1 * u.y;
            acc1.z += p1 * u.z; acc1.w += p1 * u.w;
        }
        float inv0 = 1.f / ssum0;
        float inv1 = 1.f / ssum1;
        int l0 = blockIdx.x * 16 + lt0;
        int l1 = blockIdx.x * 16 + lt1;
        float4* op0 = (float4*)(out + (((size_t)(b * L_ + l0) * H_) + h) * E_) + lane16;
        float4* op1 = (float4*)(out + (((size_t)(b * L_ + l1) * H_) + h) * E_) + lane16;
        *op0 = make_float4(acc0.x * inv0 + bb.x, acc0.y * inv0 + bb.y,
                           acc0.z * inv0 + bb.z, acc0.w * inv0 + bb.w);
        *op1 = make_float4(acc1.x * inv1 + bb.x, acc1.y * inv1 + bb.y,
                           acc1.z * inv1 + bb.z, acc1.w * inv1 + bb.w);
    }
}

extern "C" void kernel_launch(void* const* d_in, const int* in_sizes, int n_in,
                              void* d_out, int out_size) {
    const float* tfq  = (const float*)d_in[0];
    const float* q    = (const float*)d_in[1];
    const float* k    = (const float*)d_in[2];
    const float* v    = (const float*)d_in[3];
    // d_in[4] = mask (unused)
    const float* W    = (const float*)d_in[5];
    const float* bias = (const float*)d_in[6];
    float* out = (float*)d_out;

    corr_tf_kernel<<<1040, 256>>>(q, k, tfq);
    topk_kernel<<<32, 256>>>();
    usel_kernel<<<dim3(32, BH_), 512>>>(W, bias, v);
    fused_kernel<<<dim3(64, BH_), 128>>>(tfq, q, k, out);
}